// round 12
// baseline (speedup 1.0000x reference)
#include <cuda_runtime.h>
#include <cuda_fp16.h>
#include <cstdint>
#include <cstddef>

#define SS 64
#define BB 32
#define HH 1024
#define EE 512
#define VV 32000
#define LL 2
#define SB (SS*BB)                 // 2048
#define BH (BB*HH)                 // 32768
#define LOGITS_N ((size_t)SB*(size_t)VV)
#define NB 128
#define TPB 256

// ---------------- device scratch ----------------
__device__ float g_h0[BH];
__device__ float g_tops[(size_t)SB*HH];
__device__ float g_pA[8][BB][HH];
__device__ float g_pB[8][BB][HH];
__device__ unsigned g_slot[NB];            // distributed barrier slots (zero-init)
__device__ __half g_Ah[(size_t)SB*HH];
__device__ __half g_Al[(size_t)SB*HH];
__device__ __half g_Bh[(size_t)VV*HH];

// ---------------- distributed grid barrier: no atomic chain ----------------
// Arrival: one release-store to own slot. Detection: 128 threads acquire-poll
// one slot each in parallel, then __syncthreads().
__device__ __forceinline__ void gbar(unsigned target) {
    __syncthreads();
    if (threadIdx.x == 0) {
        __threadfence();
        asm volatile("st.release.gpu.global.u32 [%0], %1;"
                     :: "l"(&g_slot[blockIdx.x]), "r"(target) : "memory");
    }
    if (threadIdx.x < NB) {
        unsigned v;
        int spin = 0;
        for (;;) {
            asm volatile("ld.acquire.gpu.global.u32 %0, [%1];"
                         : "=r"(v) : "l"(&g_slot[threadIdx.x]) : "memory");
            if ((int)(v - target) >= 0) break;
            if (++spin > 4) __nanosleep(64);
        }
    }
    __syncthreads();
}

__device__ __forceinline__ float4 ldcg4(const float* p) {
    return __ldcg((const float4*)p);
}

// ---------------- persistent RNN ----------------
#define OFF_WX0 0
#define OFF_WH0 4352
#define OFF_WX1 12800
#define OFF_WH1 21248
#define OFF_BUFA 29696
#define OFF_BUFB 33920
#define SMEM_FLOATS 38144
#define SMEM_BYTES (SMEM_FLOATS*4)

template<int KLEN, int WS>
__device__ __forceinline__ void dotacc(const float* __restrict__ w,
                                       const float* __restrict__ x,
                                       int hp, int bq, float a[2][4]) {
    const float* w0 = w + (2*hp)*WS;
    const float* w1 = w0 + WS;
    const float* xb = x + 4*bq*132;
    #pragma unroll 8
    for (int k = 0; k < KLEN; k += 4) {
        float4 wv0 = *(const float4*)(w0 + k);
        float4 wv1 = *(const float4*)(w1 + k);
        #pragma unroll
        for (int j = 0; j < 4; j++) {
            float4 xv = *(const float4*)(xb + j*132 + k);
            a[0][j] += wv0.x*xv.x + wv0.y*xv.y + wv0.z*xv.z + wv0.w*xv.w;
            a[1][j] += wv1.x*xv.x + wv1.y*xv.y + wv1.z*xv.z + wv1.w*xv.w;
        }
    }
}

__global__ void __launch_bounds__(TPB) k_rnn(
    const int* __restrict__ tok, const float* __restrict__ hidden,
    const float* __restrict__ emb,
    const float* __restrict__ Wx0, const float* __restrict__ Wh0, const float* __restrict__ bh0,
    const float* __restrict__ Wx1, const float* __restrict__ Wh1, const float* __restrict__ bh1)
{
    extern __shared__ float sm[];
    float* swx0 = sm + OFF_WX0;
    float* swh0 = sm + OFF_WH0;
    float* swx1 = sm + OFF_WX1;
    float* swh1 = sm + OFF_WH1;
    float* bufA = sm + OFF_BUFA;
    float* bufB = sm + OFF_BUFB;
    __shared__ int toks[32];

    int tid = threadIdx.x;
    int bi  = blockIdx.x;
    int hg  = bi >> 3;
    int kc  = bi & 7;
    unsigned fbase;   // epoch base from previous launch (all slots equal at launch end)
    asm volatile("ld.global.u32 %0, [%1];" : "=r"(fbase) : "l"(&g_slot[bi]));

    for (int i = tid; i < 64*64; i += TPB) {
        int h = i >> 6, c = i & 63;
        swx0[h*68 + c] = Wx0[(size_t)(hg*64+h)*EE + kc*64 + c];
    }
    for (int i = tid; i < 64*128; i += TPB) {
        int h = i >> 7, c = i & 127;
        size_t gof = (size_t)(hg*64+h)*HH + kc*128 + c;
        swh0[h*132 + c] = Wh0[gof];
        swx1[h*132 + c] = Wx1[gof];
        swh1[h*132 + c] = Wh1[gof];
    }
    {
        int idx = bi*256 + tid;
        g_h0[idx] = hidden[idx];
    }

    int hp = tid >> 3;
    int bq = tid & 7;
    unsigned bar = 0;

    gbar(fbase + (++bar));

    for (int s = 0; s < SS; s++) {
        if (s > 0) {
            int idx = bi*256 + tid;
            float v = bh1[idx & (HH-1)];
            #pragma unroll
            for (int c = 0; c < 8; c++) v += __ldcg(&g_pB[c][idx>>10][idx & (HH-1)]);
            g_tops[(size_t)(s-1)*BH + idx] = tanhf(v);
        }
        if (tid < 32) toks[tid] = tok[s*BB + tid];
        __syncthreads();
        for (int i = tid; i < 32*16; i += TPB) {
            int b = i >> 4, c4 = i & 15;
            float4 v = *(const float4*)&emb[(size_t)toks[b]*EE + kc*64 + c4*4];
            *(float4*)&bufA[b*132 + c4*4] = v;
        }
        for (int i = tid; i < 32*32; i += TPB) {
            int b = i >> 5, c4 = i & 31;
            float4 v = ldcg4(&g_h0[(size_t)b*HH + kc*128 + c4*4]);
            *(float4*)&bufB[b*132 + c4*4] = v;
        }
        __syncthreads();
        {
            float a[2][4] = {{0.f,0.f,0.f,0.f},{0.f,0.f,0.f,0.f}};
            dotacc<64,68>(swx0, bufA, hp, bq, a);
            dotacc<128,132>(swh0, bufB, hp, bq, a);
            int hb = hg*64 + 2*hp;
            #pragma unroll
            for (int j = 0; j < 4; j++)
                *(float2*)&g_pA[kc][4*bq+j][hb] = make_float2(a[0][j], a[1][j]);
        }
        gbar(fbase + (++bar));

        for (int i = tid; i < 32*32; i += TPB) {
            int b = i >> 5, c4 = i & 31;
            int h = kc*128 + c4*4;
            float4 v = ldcg4(&g_pA[0][b][h]);
            #pragma unroll
            for (int c = 1; c < 8; c++) {
                float4 p = ldcg4(&g_pA[c][b][h]);
                v.x += p.x; v.y += p.y; v.z += p.z; v.w += p.w;
            }
            v.x = tanhf(v.x + bh0[h+0]);
            v.y = tanhf(v.y + bh0[h+1]);
            v.z = tanhf(v.z + bh0[h+2]);
            v.w = tanhf(v.w + bh0[h+3]);
            *(float4*)&bufA[b*132 + c4*4] = v;
            if (hg == 0) *(float4*)&g_h0[(size_t)b*HH + h] = v;
        }
        {
            const float* h1src = (s == 0) ? (hidden + BH) : (g_tops + (size_t)(s-1)*BH);
            for (int i = tid; i < 32*32; i += TPB) {
                int b = i >> 5, c4 = i & 31;
                float4 v = ldcg4(&h1src[(size_t)b*HH + kc*128 + c4*4]);
                *(float4*)&bufB[b*132 + c4*4] = v;
            }
        }
        __syncthreads();
        {
            float a[2][4] = {{0.f,0.f,0.f,0.f},{0.f,0.f,0.f,0.f}};
            dotacc<128,132>(swx1, bufA, hp, bq, a);
            dotacc<128,132>(swh1, bufB, hp, bq, a);
            int hb = hg*64 + 2*hp;
            #pragma unroll
            for (int j = 0; j < 4; j++)
                *(float2*)&g_pB[kc][4*bq+j][hb] = make_float2(a[0][j], a[1][j]);
        }
        gbar(fbase + (++bar));
    }

    {
        int idx = bi*256 + tid;
        float v = bh1[idx & (HH-1)];
        #pragma unroll
        for (int c = 0; c < 8; c++) v += __ldcg(&g_pB[c][idx>>10][idx & (HH-1)]);
        g_tops[(size_t)63*BH + idx] = tanhf(v);
    }
}

// ---------------- hi/lo fp16 split ----------------
__global__ void k_splitA() {
    size_t n = (size_t)SB * HH;
    for (size_t i = blockIdx.x * 256ull + threadIdx.x; i < n; i += gridDim.x * 256ull) {
        float v = g_tops[i];
        __half h = __float2half(v);
        g_Ah[i] = h;
        g_Al[i] = __float2half(v - __half2float(h));
    }
}
__global__ void k_splitB(const float* __restrict__ W) {
    size_t n = (size_t)VV * HH;
    for (size_t i = blockIdx.x * 256ull + threadIdx.x; i < n; i += gridDim.x * 256ull) {
        g_Bh[i] = __float2half(W[i]);
    }
}

// ---------------- logits GEMM: fp16 2-term split (unchanged from round 11) ----------------
#define GROW 40
#define STAGE_U (384*GROW)
#define GSMEM_BYTES (2*STAGE_U*2)     // 61440

__device__ __forceinline__ void cpa16(unsigned saddr, const void* g) {
    asm volatile("cp.async.cg.shared.global [%0], [%1], 16;" :: "r"(saddr), "l"(g));
}
__device__ __forceinline__ void cp_commit() { asm volatile("cp.async.commit_group;"); }
__device__ __forceinline__ void cp_wait0()  { asm volatile("cp.async.wait_group 0;"); }

__device__ __forceinline__ void ldsm4(unsigned addr, unsigned* r) {
    asm volatile("ldmatrix.sync.aligned.m8n8.x4.shared.b16 {%0,%1,%2,%3}, [%4];"
        : "=r"(r[0]), "=r"(r[1]), "=r"(r[2]), "=r"(r[3]) : "r"(addr));
}
__device__ __forceinline__ void mma16816(float* c, const unsigned* a, const unsigned* b) {
    asm volatile(
        "mma.sync.aligned.m16n8k16.row.col.f32.f16.f16.f32 "
        "{%0,%1,%2,%3},{%4,%5,%6,%7},{%8,%9},{%0,%1,%2,%3};"
        : "+f"(c[0]), "+f"(c[1]), "+f"(c[2]), "+f"(c[3])
        : "r"(a[0]), "r"(a[1]), "r"(a[2]), "r"(a[3]), "r"(b[0]), "r"(b[1]));
}

__global__ void __launch_bounds__(256) k_gemm(const float* __restrict__ bias,
                                              float* __restrict__ C) {
    extern __shared__ __half gsm[];
    unsigned smem_base = (unsigned)__cvta_generic_to_shared(gsm);

    int tid = threadIdx.x;
    int bm = blockIdx.x;
    int bn = blockIdx.y;

    const __half* pAh = g_Ah + (size_t)(bm*128)*HH;
    const __half* pAl = g_Al + (size_t)(bm*128)*HH;
    const __half* pBh = g_Bh + (size_t)(bn*128)*HH;

    auto load_stage = [&](int st, int kt) {
        unsigned base = smem_base + (unsigned)(st*STAGE_U)*2;
        #pragma unroll
        for (int i = 0; i < 4; i++) {
            int id = tid + i*256;
            int row = id >> 2, c = id & 3;
            const __half* src = ((row < 128) ? pAh + (size_t)row*HH
                                             : pAl + (size_t)(row-128)*HH)
                                + kt*32 + c*8;
            cpa16(base + (unsigned)(row*GROW + c*8)*2, src);
        }
        #pragma unroll
        for (int i = 0; i < 2; i++) {
            int id = tid + i*256;
            int row = id >> 2, c = id & 3;
            const __half* src = pBh + (size_t)row*HH + kt*32 + c*8;
            cpa16(base + (unsigned)(256*GROW + row*GROW + c*8)*2, src);
        }
        cp_commit();
    };

    int lane = tid & 31, warp = tid >> 5;
    int wm = warp >> 2;
    int wn = warp & 3;
    int moff = wm * 64, noff = wn * 32;

    int arow = lane & 15;
    int akh  = (lane >= 16) ? 8 : 0;
    int brow = (lane & 7) + ((lane >= 16) ? 8 : 0);
    int bkh  = (lane & 8) ? 8 : 0;

    float acc[4][4][4];
    #pragma unroll
    for (int mt = 0; mt < 4; mt++)
        #pragma unroll
        for (int nt = 0; nt < 4; nt++)
            #pragma unroll
            for (int r = 0; r < 4; r++) acc[mt][nt][r] = 0.f;

    load_stage(0, 0);

    #pragma unroll 1
    for (int kt = 0; kt < 32; kt++) {
        cp_wait0();
        __syncthreads();
        if (kt + 1 < 32) load_stage((kt + 1) & 1, kt + 1);

        unsigned aB = smem_base + (unsigned)((kt & 1)*STAGE_U)*2;
        unsigned bB = aB + (unsigned)(256*GROW)*2;

        #pragma unroll
        for (int kk = 0; kk < 2; kk++) {
            unsigned ah[4][4], al[4][4], bh[2][4];
            #pragma unroll
            for (int mt = 0; mt < 4; mt++) {
                unsigned ra = aB + (unsigned)((moff + mt*16 + arow)*GROW + kk*16 + akh)*2;
                ldsm4(ra, ah[mt]);
                ldsm4(ra + (unsigned)(128*GROW)*2, al[mt]);
            }
            #pragma unroll
            for (int q = 0; q < 2; q++) {
                unsigned rb = bB + (unsigned)((noff + q*16 + brow)*GROW + kk*16 + bkh)*2;
                ldsm4(rb, bh[q]);
            }
            #pragma unroll
            for (int mt = 0; mt < 4; mt++)
                #pragma unroll
                for (int nt = 0; nt < 4; nt++) {
                    const unsigned* vh = &bh[nt >> 1][(nt & 1)*2];
                    mma16816(acc[mt][nt], ah[mt], vh);
                    mma16816(acc[mt][nt], al[mt], vh);
                }
        }
    }

    int g = lane >> 2, t2 = lane & 3;
    #pragma unroll
    for (int mt = 0; mt < 4; mt++)
        #pragma unroll
        for (int nt = 0; nt < 4; nt++) {
            int m = bm*128 + moff + mt*16 + g;
            int n = bn*128 + noff + nt*8 + t2*2;
            float b0 = __ldg(&bias[n]), b1 = __ldg(&bias[n+1]);
            size_t o = (size_t)m * VV + n;
            C[o]     = acc[mt][nt][0] + b0;
            C[o + 1] = acc[mt][nt][1] + b1;
            size_t o2 = o + (size_t)8 * VV;
            C[o2]     = acc[mt][nt][2] + b0;
            C[o2 + 1] = acc[mt][nt][3] + b1;
        }
}

// ---------------- hidden_final output ----------------
__global__ void k_hidden(float* __restrict__ out) {
    int i = blockIdx.x * 256 + threadIdx.x;
    out[i]      = g_h0[i];
    out[BH + i] = g_tops[(size_t)63*BH + i];
}

// ---------------- launch ----------------
extern "C" void kernel_launch(void* const* d_in, const int* in_sizes, int n_in,
                              void* d_out, int out_size) {
    const int*   inputs = (const int*)d_in[0];
    const float* hidden = (const float*)d_in[1];
    const float* emb    = (const float*)d_in[2];
    const float* Wx0    = (const float*)d_in[3];
    const float* Wh0    = (const float*)d_in[4];
    const float* bh0    = (const float*)d_in[5];
    const float* Wx1    = (const float*)d_in[6];
    const float* Wh1    = (const float*)d_in[7];
    const float* bh1    = (const float*)d_in[8];
    const float* Wout   = (const float*)d_in[9];
    const float* bout   = (const float*)d_in[10];
    float* out = (float*)d_out;

    static bool attr_set = false;
    if (!attr_set) {
        cudaFuncSetAttribute(k_rnn,  cudaFuncAttributeMaxDynamicSharedMemorySize, SMEM_BYTES);
        cudaFuncSetAttribute(k_gemm, cudaFuncAttributeMaxDynamicSharedMemorySize, GSMEM_BYTES);
        attr_set = true;
    }

    k_splitB<<<2048, 256>>>(Wout);
    k_rnn<<<NB, TPB, SMEM_BYTES>>>(inputs, hidden, emb, Wx0, Wh0, bh0, Wx1, Wh1, bh1);
    k_splitA<<<2048, 256>>>();
    dim3 grid(SB / 128, VV / 128);
    k_gemm<<<grid, 256, GSMEM_BYTES>>>(bout, out);
    if ((size_t)out_size >= LOGITS_N + (size_t)LL * BH)
        k_hidden<<<128, 256>>>(out + LOGITS_N);
}

// round 13
// speedup vs baseline: 1.8458x; 1.8458x over previous
#include <cuda_runtime.h>
#include <cuda_fp16.h>
#include <cstdint>
#include <cstddef>

#define SS 64
#define BB 32
#define HH 1024
#define EE 512
#define VV 32000
#define LL 2
#define SB (SS*BB)                 // 2048
#define BH (BB*HH)                 // 32768
#define LOGITS_N ((size_t)SB*(size_t)VV)
#define NB 128
#define TPB 256

// ---------------- device scratch ----------------
__device__ float g_h0[BH];
__device__ float g_tops[(size_t)SB*HH];
__device__ float g_pA[8][BB][HH];
__device__ float g_pB[8][BB][HH];
__device__ unsigned g_count = 0;
__device__ unsigned g_flag  = 0;
__device__ __half g_Ah[(size_t)SB*HH];
__device__ __half g_Al[(size_t)SB*HH];
__device__ __half g_Bh[(size_t)VV*HH];

// ---------------- grid barrier (round-11 central atomic, known-good) ----------------
__device__ __forceinline__ void gbar(unsigned target) {
    __syncthreads();
    if (threadIdx.x == 0) {
        __threadfence();
        unsigned old = atomicAdd(&g_count, 1);
        if (old == NB - 1) {
            g_count = 0;
            __threadfence();
            atomicAdd(&g_flag, 1);
        } else {
            while ((int)(*(volatile unsigned*)&g_flag - target) < 0) { }
        }
    }
    __syncthreads();
}

__device__ __forceinline__ float4 ldcg4(const float* p) {
    return __ldcg((const float4*)p);
}

// x-buffer swizzle: float4 column c4 of batch-row b stored at column (c4 ^ (b>>2)).
// Makes the 8 distinct bq lanes in dotacc hit 8 distinct 16B banks (proof in header note).
__device__ __forceinline__ int xswz(int b, int c4) { return (c4 ^ (b >> 2)) << 2; }

// ---------------- persistent RNN ----------------
#define OFF_WX0 0
#define OFF_WH0 4352
#define OFF_WX1 12800
#define OFF_WH1 21248
#define OFF_BUFA 29696
#define OFF_BUFB 33920
#define SMEM_FLOATS 38144
#define SMEM_BYTES (SMEM_FLOATS*4)

template<int KLEN, int WS>
__device__ __forceinline__ void dotacc(const float* __restrict__ w,
                                       const float* __restrict__ x,
                                       int hp, int bq, float a[2][4]) {
    const float* w0 = w + (2*hp)*WS;
    const float* w1 = w0 + WS;
    #pragma unroll 8
    for (int kg = 0; kg < KLEN/4; kg++) {
        float4 wv0 = *(const float4*)(w0 + kg*4);
        float4 wv1 = *(const float4*)(w1 + kg*4);
        int sw = ((kg ^ bq) << 2);
        #pragma unroll
        for (int j = 0; j < 4; j++) {
            float4 xv = *(const float4*)(x + (4*bq + j)*132 + sw);
            a[0][j] += wv0.x*xv.x + wv0.y*xv.y + wv0.z*xv.z + wv0.w*xv.w;
            a[1][j] += wv1.x*xv.x + wv1.y*xv.y + wv1.z*xv.z + wv1.w*xv.w;
        }
    }
}

__global__ void __launch_bounds__(TPB) k_rnn(
    const int* __restrict__ tok, const float* __restrict__ hidden,
    const float* __restrict__ emb,
    const float* __restrict__ Wx0, const float* __restrict__ Wh0, const float* __restrict__ bh0,
    const float* __restrict__ Wx1, const float* __restrict__ Wh1, const float* __restrict__ bh1)
{
    extern __shared__ float sm[];
    float* swx0 = sm + OFF_WX0;
    float* swh0 = sm + OFF_WH0;
    float* swx1 = sm + OFF_WX1;
    float* swh1 = sm + OFF_WH1;
    float* bufA = sm + OFF_BUFA;
    float* bufB = sm + OFF_BUFB;
    __shared__ int toks[32];

    int tid = threadIdx.x;
    int bi  = blockIdx.x;
    int hg  = bi >> 3;
    int kc  = bi & 7;
    unsigned fbase = *(volatile unsigned*)&g_flag;

    for (int i = tid; i < 64*64; i += TPB) {
        int h = i >> 6, c = i & 63;
        swx0[h*68 + c] = Wx0[(size_t)(hg*64+h)*EE + kc*64 + c];
    }
    for (int i = tid; i < 64*128; i += TPB) {
        int h = i >> 7, c = i & 127;
        size_t gof = (size_t)(hg*64+h)*HH + kc*128 + c;
        swh0[h*132 + c] = Wh0[gof];
        swx1[h*132 + c] = Wx1[gof];
        swh1[h*132 + c] = Wh1[gof];
    }
    {
        int idx = bi*256 + tid;
        g_h0[idx] = hidden[idx];
    }

    int hp = tid >> 3;
    int bq = tid & 7;
    unsigned bar = 0;

    gbar(fbase + (++bar));

    for (int s = 0; s < SS; s++) {
        if (s > 0) {
            int idx = bi*256 + tid;
            float v = bh1[idx & (HH-1)];
            #pragma unroll
            for (int c = 0; c < 8; c++) v += __ldcg(&g_pB[c][idx>>10][idx & (HH-1)]);
            g_tops[(size_t)(s-1)*BH + idx] = tanhf(v);
        }
        if (tid < 32) toks[tid] = tok[s*BB + tid];
        __syncthreads();
        for (int i = tid; i < 32*16; i += TPB) {
            int b = i >> 4, c4 = i & 15;
            float4 v = *(const float4*)&emb[(size_t)toks[b]*EE + kc*64 + c4*4];
            *(float4*)&bufA[b*132 + xswz(b, c4)] = v;
        }
        for (int i = tid; i < 32*32; i += TPB) {
            int b = i >> 5, c4 = i & 31;
            float4 v = ldcg4(&g_h0[(size_t)b*HH + kc*128 + c4*4]);
            *(float4*)&bufB[b*132 + xswz(b, c4)] = v;
        }
        __syncthreads();
        {
            float a[2][4] = {{0.f,0.f,0.f,0.f},{0.f,0.f,0.f,0.f}};
            dotacc<64,68>(swx0, bufA, hp, bq, a);
            dotacc<128,132>(swh0, bufB, hp, bq, a);
            int hb = hg*64 + 2*hp;
            #pragma unroll
            for (int j = 0; j < 4; j++)
                *(float2*)&g_pA[kc][4*bq+j][hb] = make_float2(a[0][j], a[1][j]);
        }
        gbar(fbase + (++bar));

        for (int i = tid; i < 32*32; i += TPB) {
            int b = i >> 5, c4 = i & 31;
            int h = kc*128 + c4*4;
            float4 v = ldcg4(&g_pA[0][b][h]);
            #pragma unroll
            for (int c = 1; c < 8; c++) {
                float4 p = ldcg4(&g_pA[c][b][h]);
                v.x += p.x; v.y += p.y; v.z += p.z; v.w += p.w;
            }
            v.x = tanhf(v.x + bh0[h+0]);
            v.y = tanhf(v.y + bh0[h+1]);
            v.z = tanhf(v.z + bh0[h+2]);
            v.w = tanhf(v.w + bh0[h+3]);
            *(float4*)&bufA[b*132 + xswz(b, c4)] = v;
            if (hg == 0) *(float4*)&g_h0[(size_t)b*HH + h] = v;
        }
        {
            const float* h1src = (s == 0) ? (hidden + BH) : (g_tops + (size_t)(s-1)*BH);
            for (int i = tid; i < 32*32; i += TPB) {
                int b = i >> 5, c4 = i & 31;
                float4 v = ldcg4(&h1src[(size_t)b*HH + kc*128 + c4*4]);
                *(float4*)&bufB[b*132 + xswz(b, c4)] = v;
            }
        }
        __syncthreads();
        {
            float a[2][4] = {{0.f,0.f,0.f,0.f},{0.f,0.f,0.f,0.f}};
            dotacc<128,132>(swx1, bufA, hp, bq, a);
            dotacc<128,132>(swh1, bufB, hp, bq, a);
            int hb = hg*64 + 2*hp;
            #pragma unroll
            for (int j = 0; j < 4; j++)
                *(float2*)&g_pB[kc][4*bq+j][hb] = make_float2(a[0][j], a[1][j]);
        }
        gbar(fbase + (++bar));
    }

    {
        int idx = bi*256 + tid;
        float v = bh1[idx & (HH-1)];
        #pragma unroll
        for (int c = 0; c < 8; c++) v += __ldcg(&g_pB[c][idx>>10][idx & (HH-1)]);
        g_tops[(size_t)63*BH + idx] = tanhf(v);
    }
}

// ---------------- hi/lo fp16 split ----------------
__global__ void k_splitA() {
    size_t n = (size_t)SB * HH;
    for (size_t i = blockIdx.x * 256ull + threadIdx.x; i < n; i += gridDim.x * 256ull) {
        float v = g_tops[i];
        __half h = __float2half(v);
        g_Ah[i] = h;
        g_Al[i] = __float2half(v - __half2float(h));
    }
}
__global__ void k_splitB(const float* __restrict__ W) {
    size_t n = (size_t)VV * HH;
    for (size_t i = blockIdx.x * 256ull + threadIdx.x; i < n; i += gridDim.x * 256ull) {
        g_Bh[i] = __float2half(W[i]);
    }
}

// ---------------- logits GEMM: fp16 2-term split (unchanged from round 11) ----------------
#define GROW 40
#define STAGE_U (384*GROW)
#define GSMEM_BYTES (2*STAGE_U*2)     // 61440

__device__ __forceinline__ void cpa16(unsigned saddr, const void* g) {
    asm volatile("cp.async.cg.shared.global [%0], [%1], 16;" :: "r"(saddr), "l"(g));
}
__device__ __forceinline__ void cp_commit() { asm volatile("cp.async.commit_group;"); }
__device__ __forceinline__ void cp_wait0()  { asm volatile("cp.async.wait_group 0;"); }

__device__ __forceinline__ void ldsm4(unsigned addr, unsigned* r) {
    asm volatile("ldmatrix.sync.aligned.m8n8.x4.shared.b16 {%0,%1,%2,%3}, [%4];"
        : "=r"(r[0]), "=r"(r[1]), "=r"(r[2]), "=r"(r[3]) : "r"(addr));
}
__device__ __forceinline__ void mma16816(float* c, const unsigned* a, const unsigned* b) {
    asm volatile(
        "mma.sync.aligned.m16n8k16.row.col.f32.f16.f16.f32 "
        "{%0,%1,%2,%3},{%4,%5,%6,%7},{%8,%9},{%0,%1,%2,%3};"
        : "+f"(c[0]), "+f"(c[1]), "+f"(c[2]), "+f"(c[3])
        : "r"(a[0]), "r"(a[1]), "r"(a[2]), "r"(a[3]), "r"(b[0]), "r"(b[1]));
}

__global__ void __launch_bounds__(256) k_gemm(const float* __restrict__ bias,
                                              float* __restrict__ C) {
    extern __shared__ __half gsm[];
    unsigned smem_base = (unsigned)__cvta_generic_to_shared(gsm);

    int tid = threadIdx.x;
    int bm = blockIdx.x;
    int bn = blockIdx.y;

    const __half* pAh = g_Ah + (size_t)(bm*128)*HH;
    const __half* pAl = g_Al + (size_t)(bm*128)*HH;
    const __half* pBh = g_Bh + (size_t)(bn*128)*HH;

    auto load_stage = [&](int st, int kt) {
        unsigned base = smem_base + (unsigned)(st*STAGE_U)*2;
        #pragma unroll
        for (int i = 0; i < 4; i++) {
            int id = tid + i*256;
            int row = id >> 2, c = id & 3;
            const __half* src = ((row < 128) ? pAh + (size_t)row*HH
                                             : pAl + (size_t)(row-128)*HH)
                                + kt*32 + c*8;
            cpa16(base + (unsigned)(row*GROW + c*8)*2, src);
        }
        #pragma unroll
        for (int i = 0; i < 2; i++) {
            int id = tid + i*256;
            int row = id >> 2, c = id & 3;
            const __half* src = pBh + (size_t)row*HH + kt*32 + c*8;
            cpa16(base + (unsigned)(256*GROW + row*GROW + c*8)*2, src);
        }
        cp_commit();
    };

    int lane = tid & 31, warp = tid >> 5;
    int wm = warp >> 2;
    int wn = warp & 3;
    int moff = wm * 64, noff = wn * 32;

    int arow = lane & 15;
    int akh  = (lane >= 16) ? 8 : 0;
    int brow = (lane & 7) + ((lane >= 16) ? 8 : 0);
    int bkh  = (lane & 8) ? 8 : 0;

    float acc[4][4][4];
    #pragma unroll
    for (int mt = 0; mt < 4; mt++)
        #pragma unroll
        for (int nt = 0; nt < 4; nt++)
            #pragma unroll
            for (int r = 0; r < 4; r++) acc[mt][nt][r] = 0.f;

    load_stage(0, 0);

    #pragma unroll 1
    for (int kt = 0; kt < 32; kt++) {
        cp_wait0();
        __syncthreads();
        if (kt + 1 < 32) load_stage((kt + 1) & 1, kt + 1);

        unsigned aB = smem_base + (unsigned)((kt & 1)*STAGE_U)*2;
        unsigned bB = aB + (unsigned)(256*GROW)*2;

        #pragma unroll
        for (int kk = 0; kk < 2; kk++) {
            unsigned ah[4][4], al[4][4], bh[2][4];
            #pragma unroll
            for (int mt = 0; mt < 4; mt++) {
                unsigned ra = aB + (unsigned)((moff + mt*16 + arow)*GROW + kk*16 + akh)*2;
                ldsm4(ra, ah[mt]);
                ldsm4(ra + (unsigned)(128*GROW)*2, al[mt]);
            }
            #pragma unroll
            for (int q = 0; q < 2; q++) {
                unsigned rb = bB + (unsigned)((noff + q*16 + brow)*GROW + kk*16 + bkh)*2;
                ldsm4(rb, bh[q]);
            }
            #pragma unroll
            for (int mt = 0; mt < 4; mt++)
                #pragma unroll
                for (int nt = 0; nt < 4; nt++) {
                    const unsigned* vh = &bh[nt >> 1][(nt & 1)*2];
                    mma16816(acc[mt][nt], ah[mt], vh);
                    mma16816(acc[mt][nt], al[mt], vh);
                }
        }
    }

    int g = lane >> 2, t2 = lane & 3;
    #pragma unroll
    for (int mt = 0; mt < 4; mt++)
        #pragma unroll
        for (int nt = 0; nt < 4; nt++) {
            int m = bm*128 + moff + mt*16 + g;
            int n = bn*128 + noff + nt*8 + t2*2;
            float b0 = __ldg(&bias[n]), b1 = __ldg(&bias[n+1]);
            size_t o = (size_t)m * VV + n;
            C[o]     = acc[mt][nt][0] + b0;
            C[o + 1] = acc[mt][nt][1] + b1;
            size_t o2 = o + (size_t)8 * VV;
            C[o2]     = acc[mt][nt][2] + b0;
            C[o2 + 1] = acc[mt][nt][3] + b1;
        }
}

// ---------------- hidden_final output ----------------
__global__ void k_hidden(float* __restrict__ out) {
    int i = blockIdx.x * 256 + threadIdx.x;
    out[i]      = g_h0[i];
    out[BH + i] = g_tops[(size_t)63*BH + i];
}

// ---------------- launch ----------------
extern "C" void kernel_launch(void* const* d_in, const int* in_sizes, int n_in,
                              void* d_out, int out_size) {
    const int*   inputs = (const int*)d_in[0];
    const float* hidden = (const float*)d_in[1];
    const float* emb    = (const float*)d_in[2];
    const float* Wx0    = (const float*)d_in[3];
    const float* Wh0    = (const float*)d_in[4];
    const float* bh0    = (const float*)d_in[5];
    const float* Wx1    = (const float*)d_in[6];
    const float* Wh1    = (const float*)d_in[7];
    const float* bh1    = (const float*)d_in[8];
    const float* Wout   = (const float*)d_in[9];
    const float* bout   = (const float*)d_in[10];
    float* out = (float*)d_out;

    static bool attr_set = false;
    if (!attr_set) {
        cudaFuncSetAttribute(k_rnn,  cudaFuncAttributeMaxDynamicSharedMemorySize, SMEM_BYTES);
        cudaFuncSetAttribute(k_gemm, cudaFuncAttributeMaxDynamicSharedMemorySize, GSMEM_BYTES);
        attr_set = true;
    }

    k_splitB<<<2048, 256>>>(Wout);
    k_rnn<<<NB, TPB, SMEM_BYTES>>>(inputs, hidden, emb, Wx0, Wh0, bh0, Wx1, Wh1, bh1);
    k_splitA<<<2048, 256>>>();
    dim3 grid(SB / 128, VV / 128);
    k_gemm<<<grid, 256, GSMEM_BYTES>>>(bout, out);
    if ((size_t)out_size >= LOGITS_N + (size_t)LL * BH)
        k_hidden<<<128, 256>>>(out + LOGITS_N);
}

// round 14
// speedup vs baseline: 2.1392x; 1.1590x over previous
#include <cuda_runtime.h>
#include <cuda_fp16.h>
#include <cstdint>
#include <cstddef>

#define SS 64
#define BB 32
#define HH 1024
#define EE 512
#define VV 32000
#define LL 2
#define SB (SS*BB)                 // 2048
#define BH (BB*HH)                 // 32768
#define LOGITS_N ((size_t)SB*(size_t)VV)
#define NB 128
#define TPB 256

// ---------------- device scratch ----------------
__device__ float g_h0[BH];
__device__ float g_tops[(size_t)SB*HH];
__device__ float g_pA[8][BB][HH];
__device__ float g_pB[8][BB][HH];
__device__ unsigned g_count = 0;
__device__ unsigned g_flag  = 0;
__device__ __half g_Ah[(size_t)SB*HH];
__device__ __half g_Bh[(size_t)VV*HH];

// ---------------- grid barrier (central atomic, known-good) ----------------
__device__ __forceinline__ void gbar(unsigned target) {
    __syncthreads();
    if (threadIdx.x == 0) {
        __threadfence();
        unsigned old = atomicAdd(&g_count, 1);
        if (old == NB - 1) {
            g_count = 0;
            __threadfence();
            atomicAdd(&g_flag, 1);
        } else {
            while ((int)(*(volatile unsigned*)&g_flag - target) < 0) { }
        }
    }
    __syncthreads();
}

__device__ __forceinline__ float4 ldcg4(const float* p) {
    return __ldcg((const float4*)p);
}

// x-buffer swizzle (conflict-free dotacc x loads)
__device__ __forceinline__ int xswz(int b, int c4) { return (c4 ^ (b >> 2)) << 2; }

// ---------------- persistent RNN (unchanged from round 13) ----------------
#define OFF_WX0 0
#define OFF_WH0 4352
#define OFF_WX1 12800
#define OFF_WH1 21248
#define OFF_BUFA 29696
#define OFF_BUFB 33920
#define SMEM_FLOATS 38144
#define SMEM_BYTES (SMEM_FLOATS*4)

template<int KLEN, int WS>
__device__ __forceinline__ void dotacc(const float* __restrict__ w,
                                       const float* __restrict__ x,
                                       int hp, int bq, float a[2][4]) {
    const float* w0 = w + (2*hp)*WS;
    const float* w1 = w0 + WS;
    #pragma unroll 8
    for (int kg = 0; kg < KLEN/4; kg++) {
        float4 wv0 = *(const float4*)(w0 + kg*4);
        float4 wv1 = *(const float4*)(w1 + kg*4);
        int sw = ((kg ^ bq) << 2);
        #pragma unroll
        for (int j = 0; j < 4; j++) {
            float4 xv = *(const float4*)(x + (4*bq + j)*132 + sw);
            a[0][j] += wv0.x*xv.x + wv0.y*xv.y + wv0.z*xv.z + wv0.w*xv.w;
            a[1][j] += wv1.x*xv.x + wv1.y*xv.y + wv1.z*xv.z + wv1.w*xv.w;
        }
    }
}

__global__ void __launch_bounds__(TPB) k_rnn(
    const int* __restrict__ tok, const float* __restrict__ hidden,
    const float* __restrict__ emb,
    const float* __restrict__ Wx0, const float* __restrict__ Wh0, const float* __restrict__ bh0,
    const float* __restrict__ Wx1, const float* __restrict__ Wh1, const float* __restrict__ bh1)
{
    extern __shared__ float sm[];
    float* swx0 = sm + OFF_WX0;
    float* swh0 = sm + OFF_WH0;
    float* swx1 = sm + OFF_WX1;
    float* swh1 = sm + OFF_WH1;
    float* bufA = sm + OFF_BUFA;
    float* bufB = sm + OFF_BUFB;
    __shared__ int toks[32];

    int tid = threadIdx.x;
    int bi  = blockIdx.x;
    int hg  = bi >> 3;
    int kc  = bi & 7;
    unsigned fbase = *(volatile unsigned*)&g_flag;

    for (int i = tid; i < 64*64; i += TPB) {
        int h = i >> 6, c = i & 63;
        swx0[h*68 + c] = Wx0[(size_t)(hg*64+h)*EE + kc*64 + c];
    }
    for (int i = tid; i < 64*128; i += TPB) {
        int h = i >> 7, c = i & 127;
        size_t gof = (size_t)(hg*64+h)*HH + kc*128 + c;
        swh0[h*132 + c] = Wh0[gof];
        swx1[h*132 + c] = Wx1[gof];
        swh1[h*132 + c] = Wh1[gof];
    }
    {
        int idx = bi*256 + tid;
        g_h0[idx] = hidden[idx];
    }

    int hp = tid >> 3;
    int bq = tid & 7;
    unsigned bar = 0;

    gbar(fbase + (++bar));

    for (int s = 0; s < SS; s++) {
        if (s > 0) {
            int idx = bi*256 + tid;
            float v = bh1[idx & (HH-1)];
            #pragma unroll
            for (int c = 0; c < 8; c++) v += __ldcg(&g_pB[c][idx>>10][idx & (HH-1)]);
            g_tops[(size_t)(s-1)*BH + idx] = tanhf(v);
        }
        if (tid < 32) toks[tid] = tok[s*BB + tid];
        __syncthreads();
        for (int i = tid; i < 32*16; i += TPB) {
            int b = i >> 4, c4 = i & 15;
            float4 v = *(const float4*)&emb[(size_t)toks[b]*EE + kc*64 + c4*4];
            *(float4*)&bufA[b*132 + xswz(b, c4)] = v;
        }
        for (int i = tid; i < 32*32; i += TPB) {
            int b = i >> 5, c4 = i & 31;
            float4 v = ldcg4(&g_h0[(size_t)b*HH + kc*128 + c4*4]);
            *(float4*)&bufB[b*132 + xswz(b, c4)] = v;
        }
        __syncthreads();
        {
            float a[2][4] = {{0.f,0.f,0.f,0.f},{0.f,0.f,0.f,0.f}};
            dotacc<64,68>(swx0, bufA, hp, bq, a);
            dotacc<128,132>(swh0, bufB, hp, bq, a);
            int hb = hg*64 + 2*hp;
            #pragma unroll
            for (int j = 0; j < 4; j++)
                *(float2*)&g_pA[kc][4*bq+j][hb] = make_float2(a[0][j], a[1][j]);
        }
        gbar(fbase + (++bar));

        for (int i = tid; i < 32*32; i += TPB) {
            int b = i >> 5, c4 = i & 31;
            int h = kc*128 + c4*4;
            float4 v = ldcg4(&g_pA[0][b][h]);
            #pragma unroll
            for (int c = 1; c < 8; c++) {
                float4 p = ldcg4(&g_pA[c][b][h]);
                v.x += p.x; v.y += p.y; v.z += p.z; v.w += p.w;
            }
            v.x = tanhf(v.x + bh0[h+0]);
            v.y = tanhf(v.y + bh0[h+1]);
            v.z = tanhf(v.z + bh0[h+2]);
            v.w = tanhf(v.w + bh0[h+3]);
            *(float4*)&bufA[b*132 + xswz(b, c4)] = v;
            if (hg == 0) *(float4*)&g_h0[(size_t)b*HH + h] = v;
        }
        {
            const float* h1src = (s == 0) ? (hidden + BH) : (g_tops + (size_t)(s-1)*BH);
            for (int i = tid; i < 32*32; i += TPB) {
                int b = i >> 5, c4 = i & 31;
                float4 v = ldcg4(&h1src[(size_t)b*HH + kc*128 + c4*4]);
                *(float4*)&bufB[b*132 + xswz(b, c4)] = v;
            }
        }
        __syncthreads();
        {
            float a[2][4] = {{0.f,0.f,0.f,0.f},{0.f,0.f,0.f,0.f}};
            dotacc<128,132>(swx1, bufA, hp, bq, a);
            dotacc<128,132>(swh1, bufB, hp, bq, a);
            int hb = hg*64 + 2*hp;
            #pragma unroll
            for (int j = 0; j < 4; j++)
                *(float2*)&g_pB[kc][4*bq+j][hb] = make_float2(a[0][j], a[1][j]);
        }
        gbar(fbase + (++bar));
    }

    {
        int idx = bi*256 + tid;
        float v = bh1[idx & (HH-1)];
        #pragma unroll
        for (int c = 0; c < 8; c++) v += __ldcg(&g_pB[c][idx>>10][idx & (HH-1)]);
        g_tops[(size_t)63*BH + idx] = tanhf(v);
    }
}

// ---------------- fp16 conversion (1-term now) ----------------
__global__ void k_splitA() {
    size_t n = (size_t)SB * HH;
    for (size_t i = blockIdx.x * 256ull + threadIdx.x; i < n; i += gridDim.x * 256ull) {
        g_Ah[i] = __float2half(g_tops[i]);
    }
}
__global__ void k_splitB(const float* __restrict__ W) {
    size_t n = (size_t)VV * HH;
    for (size_t i = blockIdx.x * 256ull + threadIdx.x; i < n; i += gridDim.x * 256ull) {
        g_Bh[i] = __float2half(W[i]);
    }
}

// ---------------- logits GEMM: plain fp16, ldmatrix + 2-stage cp.async ----------------
// C = Ah * Bh^T. Error ~ sqrt(2) x round-11's B-only error ≈ 3e-4 << 1e-3.
// Block tile 128x128x32, 8 warps (2m x 4n), warp tile 64x32. 40KB smem.
#define GROW 40                       // smem row stride in u16 (80B, LDSM conflict-free)
#define STAGE_U (256*GROW)            // 128 A rows + 128 B rows per stage
#define GSMEM_BYTES (2*STAGE_U*2)     // 40960

__device__ __forceinline__ void cpa16(unsigned saddr, const void* g) {
    asm volatile("cp.async.cg.shared.global [%0], [%1], 16;" :: "r"(saddr), "l"(g));
}
__device__ __forceinline__ void cp_commit() { asm volatile("cp.async.commit_group;"); }
__device__ __forceinline__ void cp_wait0()  { asm volatile("cp.async.wait_group 0;"); }

__device__ __forceinline__ void ldsm4(unsigned addr, unsigned* r) {
    asm volatile("ldmatrix.sync.aligned.m8n8.x4.shared.b16 {%0,%1,%2,%3}, [%4];"
        : "=r"(r[0]), "=r"(r[1]), "=r"(r[2]), "=r"(r[3]) : "r"(addr));
}
__device__ __forceinline__ void mma16816(float* c, const unsigned* a, const unsigned* b) {
    asm volatile(
        "mma.sync.aligned.m16n8k16.row.col.f32.f16.f16.f32 "
        "{%0,%1,%2,%3},{%4,%5,%6,%7},{%8,%9},{%0,%1,%2,%3};"
        : "+f"(c[0]), "+f"(c[1]), "+f"(c[2]), "+f"(c[3])
        : "r"(a[0]), "r"(a[1]), "r"(a[2]), "r"(a[3]), "r"(b[0]), "r"(b[1]));
}

__global__ void __launch_bounds__(256) k_gemm(const float* __restrict__ bias,
                                              float* __restrict__ C) {
    extern __shared__ __half gsm[];
    unsigned smem_base = (unsigned)__cvta_generic_to_shared(gsm);

    int tid = threadIdx.x;
    int bm = blockIdx.x;       // fast dim: wave shares B via L2
    int bn = blockIdx.y;

    const __half* pAh = g_Ah + (size_t)(bm*128)*HH;
    const __half* pBh = g_Bh + (size_t)(bn*128)*HH;

    auto load_stage = [&](int st, int kt) {
        unsigned base = smem_base + (unsigned)(st*STAGE_U)*2;
        #pragma unroll
        for (int i = 0; i < 2; i++) {               // A: 128 rows
            int id = tid + i*256;
            int row = id >> 2, c = id & 3;
            const __half* src = pAh + (size_t)row*HH + kt*32 + c*8;
            cpa16(base + (unsigned)(row*GROW + c*8)*2, src);
        }
        #pragma unroll
        for (int i = 0; i < 2; i++) {               // B: 128 rows
            int id = tid + i*256;
            int row = id >> 2, c = id & 3;
            const __half* src = pBh + (size_t)row*HH + kt*32 + c*8;
            cpa16(base + (unsigned)(128*GROW + row*GROW + c*8)*2, src);
        }
        cp_commit();
    };

    int lane = tid & 31, warp = tid >> 5;
    int wm = warp >> 2;            // 0..1
    int wn = warp & 3;             // 0..3
    int moff = wm * 64, noff = wn * 32;

    int arow = lane & 15;
    int akh  = (lane >= 16) ? 8 : 0;
    int brow = (lane & 7) + ((lane >= 16) ? 8 : 0);
    int bkh  = (lane & 8) ? 8 : 0;

    float acc[4][4][4];
    #pragma unroll
    for (int mt = 0; mt < 4; mt++)
        #pragma unroll
        for (int nt = 0; nt < 4; nt++)
            #pragma unroll
            for (int r = 0; r < 4; r++) acc[mt][nt][r] = 0.f;

    load_stage(0, 0);

    #pragma unroll 1
    for (int kt = 0; kt < 32; kt++) {
        cp_wait0();
        __syncthreads();
        if (kt + 1 < 32) load_stage((kt + 1) & 1, kt + 1);

        unsigned aB = smem_base + (unsigned)((kt & 1)*STAGE_U)*2;
        unsigned bB = aB + (unsigned)(128*GROW)*2;

        #pragma unroll
        for (int kk = 0; kk < 2; kk++) {
            unsigned ah[4][4], bh[2][4];
            #pragma unroll
            for (int mt = 0; mt < 4; mt++) {
                unsigned ra = aB + (unsigned)((moff + mt*16 + arow)*GROW + kk*16 + akh)*2;
                ldsm4(ra, ah[mt]);
            }
            #pragma unroll
            for (int q = 0; q < 2; q++) {
                unsigned rb = bB + (unsigned)((noff + q*16 + brow)*GROW + kk*16 + bkh)*2;
                ldsm4(rb, bh[q]);
            }
            #pragma unroll
            for (int mt = 0; mt < 4; mt++)
                #pragma unroll
                for (int nt = 0; nt < 4; nt++) {
                    const unsigned* vh = &bh[nt >> 1][(nt & 1)*2];
                    mma16816(acc[mt][nt], ah[mt], vh);
                }
        }
    }

    int g = lane >> 2, t2 = lane & 3;
    #pragma unroll
    for (int mt = 0; mt < 4; mt++)
        #pragma unroll
        for (int nt = 0; nt < 4; nt++) {
            int m = bm*128 + moff + mt*16 + g;
            int n = bn*128 + noff + nt*8 + t2*2;
            float b0 = __ldg(&bias[n]), b1 = __ldg(&bias[n+1]);
            size_t o = (size_t)m * VV + n;
            C[o]     = acc[mt][nt][0] + b0;
            C[o + 1] = acc[mt][nt][1] + b1;
            size_t o2 = o + (size_t)8 * VV;
            C[o2]     = acc[mt][nt][2] + b0;
            C[o2 + 1] = acc[mt][nt][3] + b1;
        }
}

// ---------------- hidden_final output ----------------
__global__ void k_hidden(float* __restrict__ out) {
    int i = blockIdx.x * 256 + threadIdx.x;
    out[i]      = g_h0[i];
    out[BH + i] = g_tops[(size_t)63*BH + i];
}

// ---------------- launch ----------------
extern "C" void kernel_launch(void* const* d_in, const int* in_sizes, int n_in,
                              void* d_out, int out_size) {
    const int*   inputs = (const int*)d_in[0];
    const float* hidden = (const float*)d_in[1];
    const float* emb    = (const float*)d_in[2];
    const float* Wx0    = (const float*)d_in[3];
    const float* Wh0    = (const float*)d_in[4];
    const float* bh0    = (const float*)d_in[5];
    const float* Wx1    = (const float*)d_in[6];
    const float* Wh1    = (const float*)d_in[7];
    const float* bh1    = (const float*)d_in[8];
    const float* Wout   = (const float*)d_in[9];
    const float* bout   = (const float*)d_in[10];
    float* out = (float*)d_out;

    static bool attr_set = false;
    if (!attr_set) {
        cudaFuncSetAttribute(k_rnn,  cudaFuncAttributeMaxDynamicSharedMemorySize, SMEM_BYTES);
        cudaFuncSetAttribute(k_gemm, cudaFuncAttributeMaxDynamicSharedMemorySize, GSMEM_BYTES);
        attr_set = true;
    }

    k_splitB<<<2048, 256>>>(Wout);
    k_rnn<<<NB, TPB, SMEM_BYTES>>>(inputs, hidden, emb, Wx0, Wh0, bh0, Wx1, Wh1, bh1);
    k_splitA<<<2048, 256>>>();
    dim3 grid(SB / 128, VV / 128);
    k_gemm<<<grid, 256, GSMEM_BYTES>>>(bout, out);
    if ((size_t)out_size >= LOGITS_N + (size_t)LL * BH)
        k_hidden<<<128, 256>>>(out + LOGITS_N);
}